// round 1
// baseline (speedup 1.0000x reference)
#include <cuda_runtime.h>
#include <math.h>

#define NG   4
#define NB   6
#define NF   8
#define NFRR 256
#define NACT 5
#define BTOT 32768

// Precomputed factorization of the relation similarity:
// sim[g,n,m]*16 = feat_n^T M_g feat_m + vt_g.feat_n + vp_g.feat_m + c_g
__device__ float g_M[NG][NF][NF];
__device__ float g_vt[NG][NF];
__device__ float g_vp[NG][NF];
__device__ float g_c[NG];

__global__ void precompute_kernel(const float* __restrict__ Wt,
                                  const float* __restrict__ bt,
                                  const float* __restrict__ Wp,
                                  const float* __restrict__ bp)
{
    int g   = blockIdx.x;
    int tid = threadIdx.x;            // 256 threads
    const float* wt = Wt + g * NFRR * NF;
    const float* wp = Wp + g * NFRR * NF;
    int ef = tid & 63;
    int q  = tid >> 6;                // 4 r-quarters
    int e  = ef >> 3, f = ef & 7;

    float acc = 0.f;
    int r0 = q * 64;
#pragma unroll 8
    for (int r = r0; r < r0 + 64; r++)
        acc = fmaf(wt[r * NF + e], wp[r * NF + f], acc);

    __shared__ float red[256];
    red[tid] = acc;
    __syncthreads();
    if (q == 0)
        g_M[g][e][f] = (red[ef] + red[64 + ef]) + (red[128 + ef] + red[192 + ef]);

    if (tid < NF) {
        float a = 0.f, c = 0.f;
        for (int r = 0; r < NFRR; r++) {
            a = fmaf(wt[r * NF + tid], bp[g * NFRR + r], a); // Wtheta^T * b_phi
            c = fmaf(bt[g * NFRR + r], wp[r * NF + tid], c); // b_theta^T * Wphi
        }
        g_vt[g][tid] = a;
        g_vp[g][tid] = c;
    }
    if (tid == NF) {
        float cc = 0.f;
        for (int r = 0; r < NFRR; r++)
            cc = fmaf(bt[g * NFRR + r], bp[g * NFRR + r], cc);
        g_c[g] = cc;
    }
}

__global__ __launch_bounds__(32) void gcn_kernel(
    const float* __restrict__ X,     // [B,6,8]
    const float* __restrict__ P,     // [B,6,2]
    const float* __restrict__ Wext,  // [8,8]
    const float* __restrict__ bext,  // [8]
    const float* __restrict__ Wgcn,  // [4,8,8]
    const float* __restrict__ Wact,  // [5,8]
    const float* __restrict__ bact,  // [5]
    float* __restrict__ out)         // [B,5]
{
    __shared__ float sWext[NF * NF], sbext[NF];
    __shared__ float sM[NG][NF * NF];
    __shared__ float svt[NG][NF], svp[NG][NF], sc[NG];
    __shared__ float sWgcn[NG][NF * NF];
    __shared__ float sWact[NACT * NF], sbact[NACT];

    int tid = threadIdx.x;
    for (int i = tid; i < NF * NF; i += 32) sWext[i] = Wext[i];
    if (tid < NF) sbext[tid] = bext[tid];
    for (int i = tid; i < NG * NF * NF; i += 32) {
        ((float*)sM)[i]    = ((const float*)g_M)[i];
        ((float*)sWgcn)[i] = Wgcn[i];
    }
    for (int i = tid; i < NG * NF; i += 32) {
        ((float*)svt)[i] = ((const float*)g_vt)[i];
        ((float*)svp)[i] = ((const float*)g_vp)[i];
    }
    if (tid < NG) sc[tid] = g_c[tid];
    for (int i = tid; i < NACT * NF; i += 32) sWact[i] = Wact[i];
    if (tid < NACT) sbact[tid] = bact[tid];
    __syncthreads();

    int b = blockIdx.x * 32 + tid;   // grid is exact: 1024*32 = 32768

    // ---- pairwise distance mask (matches ref:  sqrt(r - 2*dot + r^T) > 4) ----
    float px[NB], py[NB], rr[NB];
    const float* p = P + b * NB * 2;
#pragma unroll
    for (int n = 0; n < NB; n++) {
        px[n] = p[2 * n];
        py[n] = p[2 * n + 1];
        rr[n] = __fmaf_rn(py[n], py[n], __fmul_rn(px[n], px[n]));
    }
    unsigned rowm[NB]; // bit m set => masked (dist > 4)
#pragma unroll
    for (int n = 0; n < NB; n++) {
        unsigned rm = 0;
#pragma unroll
        for (int m = 0; m < NB; m++) {
            float dot  = __fmaf_rn(py[n], py[m], __fmul_rn(px[n], px[m]));
            float d2   = __fadd_rn(__fsub_rn(rr[n], __fmul_rn(2.0f, dot)), rr[m]);
            float dist = __fsqrt_rn(d2);
            if (dist > 4.0f) rm |= (1u << m);
        }
        rowm[n] = rm;
    }

    // ---- feature extension: feat = relu(X @ Wext^T + bext) ----
    const float* xb = X + b * NB * NF;
    float feat[NB][NF];
#pragma unroll
    for (int n = 0; n < NB; n++) {
        float xr[NF];
#pragma unroll
        for (int f = 0; f < NF; f++) xr[f] = xb[n * NF + f];
#pragma unroll
        for (int f = 0; f < NF; f++) {
            float a = sbext[f];
#pragma unroll
            for (int e = 0; e < NF; e++) a = fmaf(xr[e], sWext[f * NF + e], a);
            feat[n][f] = fmaxf(a, 0.0f);
        }
    }

    // ---- relation graphs: accumulate relu(agg @ Wgcn^T) over g ----
    float gsum[NB][NF];
#pragma unroll
    for (int n = 0; n < NB; n++)
#pragma unroll
        for (int f = 0; f < NF; f++) gsum[n][f] = 0.0f;

    for (int g = 0; g < NG; g++) {
        float sphi[NB];
#pragma unroll
        for (int m = 0; m < NB; m++) {
            float a = 0.f;
#pragma unroll
            for (int f = 0; f < NF; f++) a = fmaf(svp[g][f], feat[m][f], a);
            sphi[m] = a;
        }
#pragma unroll
        for (int n = 0; n < NB; n++) {
            // t = feat_n @ M_g ;  st = c_g + vt_g . feat_n
            float t[NF];
#pragma unroll
            for (int f = 0; f < NF; f++) {
                float a = 0.f;
#pragma unroll
                for (int e = 0; e < NF; e++) a = fmaf(feat[n][e], sM[g][e * NF + f], a);
                t[f] = a;
            }
            float st = sc[g];
#pragma unroll
            for (int f = 0; f < NF; f++) st = fmaf(svt[g][f], feat[n][f], st);

            float s[NB];
#pragma unroll
            for (int m = 0; m < NB; m++) {
                float a = st + sphi[m];
#pragma unroll
                for (int f = 0; f < NF; f++) a = fmaf(t[f], feat[m][f], a);
                s[m] = a * 0.0625f; // / sqrt(256)
            }

            unsigned rm = rowm[n];
            float mx = -3.402823466e38f;
#pragma unroll
            for (int m = 0; m < NB; m++)
                if (!((rm >> m) & 1u)) mx = fmaxf(mx, s[m]);
            float pr[NB];
            float psum = 0.f;
#pragma unroll
            for (int m = 0; m < NB; m++) {
                float e_ = ((rm >> m) & 1u) ? 0.0f : __expf(s[m] - mx);
                pr[m] = e_;
                psum += e_;
            }
            float inv = 1.0f / psum;

            float agg[NF];
#pragma unroll
            for (int f = 0; f < NF; f++) agg[f] = 0.f;
#pragma unroll
            for (int m = 0; m < NB; m++) {
                float w = pr[m] * inv;
#pragma unroll
                for (int f = 0; f < NF; f++) agg[f] = fmaf(w, feat[m][f], agg[f]);
            }
#pragma unroll
            for (int o = 0; o < NF; o++) {
                float a = 0.f;
#pragma unroll
                for (int f = 0; f < NF; f++) a = fmaf(agg[f], sWgcn[g][o * NF + f], a);
                gsum[n][o] += fmaxf(a, 0.0f);
            }
        }
    }

    // ---- residual + max-pool over boxes + activity head ----
    float pooled[NF];
#pragma unroll
    for (int f = 0; f < NF; f++) pooled[f] = -3.402823466e38f;
#pragma unroll
    for (int n = 0; n < NB; n++) {
#pragma unroll
        for (int f = 0; f < NF; f++) {
            float st = fmaf(gsum[n][f], 0.25f, xb[n * NF + f]); // mean over NG=4 + residual
            pooled[f] = fmaxf(pooled[f], st);
        }
    }

    float* ob = out + b * NACT;
#pragma unroll
    for (int a = 0; a < NACT; a++) {
        float acc = sbact[a];
#pragma unroll
        for (int f = 0; f < NF; f++) acc = fmaf(pooled[f], sWact[a * NF + f], acc);
        ob[a] = acc;
    }
}

extern "C" void kernel_launch(void* const* d_in, const int* in_sizes, int n_in,
                              void* d_out, int out_size)
{
    const float* X    = (const float*)d_in[0];
    const float* P    = (const float*)d_in[1];
    const float* Wext = (const float*)d_in[2];
    const float* bext = (const float*)d_in[3];
    const float* Wt   = (const float*)d_in[4];
    const float* bt   = (const float*)d_in[5];
    const float* Wp   = (const float*)d_in[6];
    const float* bp   = (const float*)d_in[7];
    const float* Wgcn = (const float*)d_in[8];
    const float* Wact = (const float*)d_in[9];
    const float* bact = (const float*)d_in[10];

    precompute_kernel<<<NG, 256>>>(Wt, bt, Wp, bp);
    gcn_kernel<<<BTOT / 32, 32>>>(X, P, Wext, bext, Wgcn, Wact, bact, (float*)d_out);
}